// round 8
// baseline (speedup 1.0000x reference)
#include <cuda_runtime.h>
#include <cuda_bf16.h>
#include <math.h>
#include <stdint.h>

#define S 4096
#define D 1024
#define H 16
#define DH 64
#define F 4096
#define N1 7168              // F + 3*D : fused MLP-in + QKV output width
#define K2 5120              // F + D   : packed activation width [h | o]
#define EPSF 1e-6f

// ---------------- scratch (device globals: alloc-free) ----------------
__device__ float g_q [S * D];
__device__ float g_k [S * D];
__device__ float g_v [S * D];

__device__ __nv_bfloat16 g_xnh[S * D], g_xnl[S * D];       // LN output planes
__device__ __nv_bfloat16 g_acth[S * K2], g_actl[S * K2];   // [h | o] planes, stride K2
__device__ __nv_bfloat16 g_qsh[S * D], g_qsl[S * D];       // q * 1/8 planes
__device__ __nv_bfloat16 g_ksh[S * D], g_ksl[S * D];       // k planes
__device__ __nv_bfloat16 g_vth[D * S], g_vtl[D * S];       // V^T planes [H*64 dims][S keys]
__device__ __nv_bfloat16 g_w1h[N1 * D], g_w1l[N1 * D];     // [w_in|wq|wk|wv]^T  [7168][1024]
__device__ __nv_bfloat16 g_w2h[D * K2], g_w2l[D * K2];     // [w_mo;w_ao]^T      [1024][5120]

// ---------------- small asm helpers (base sm_103 instructions) ----------------
__device__ __forceinline__ uint32_t smem_u32(const void* p) {
    uint32_t a;
    asm("{ .reg .u64 t; cvta.to.shared.u64 t, %1; cvt.u32.u64 %0, t; }" : "=r"(a) : "l"(p));
    return a;
}
__device__ __forceinline__ void cp16(uint32_t d, const void* s) {
    asm volatile("cp.async.cg.shared.global [%0], [%1], 16;" :: "r"(d), "l"(s));
}
#define CP_COMMIT() asm volatile("cp.async.commit_group;" ::: "memory")
#define CP_WAIT1()  asm volatile("cp.async.wait_group 1;" ::: "memory")
#define CP_WAIT0()  asm volatile("cp.async.wait_group 0;" ::: "memory")

__device__ __forceinline__ void ldmx4(uint32_t* r, uint32_t a) {
    asm volatile("ldmatrix.sync.aligned.m8n8.x4.shared.b16 {%0,%1,%2,%3}, [%4];"
                 : "=r"(r[0]), "=r"(r[1]), "=r"(r[2]), "=r"(r[3]) : "r"(a));
}
__device__ __forceinline__ void ldmx2(uint32_t* r, uint32_t a) {
    asm volatile("ldmatrix.sync.aligned.m8n8.x2.shared.b16 {%0,%1}, [%2];"
                 : "=r"(r[0]), "=r"(r[1]) : "r"(a));
}
__device__ __forceinline__ void mma16816(float* c, const uint32_t* a, const uint32_t* b) {
    asm volatile("mma.sync.aligned.m16n8k16.row.col.f32.bf16.bf16.f32 "
                 "{%0,%1,%2,%3}, {%4,%5,%6,%7}, {%8,%9}, {%0,%1,%2,%3};"
                 : "+f"(c[0]), "+f"(c[1]), "+f"(c[2]), "+f"(c[3])
                 : "r"(a[0]), "r"(a[1]), "r"(a[2]), "r"(a[3]), "r"(b[0]), "r"(b[1]));
}

__device__ __forceinline__ float gelu_f(float x) {
    float x3 = x * x * x;
    return 0.5f * x * (1.f + tanhf(0.7978845608028654f * (x + 0.044715f * x3)));
}

__device__ __forceinline__ void packsplit(uint32_t& hi, uint32_t& lo, float a, float b) {
    __nv_bfloat162 h = __floats2bfloat162_rn(a, b);
    float r0 = a - __bfloat162float(__low2bfloat16(h));
    float r1 = b - __bfloat162float(__high2bfloat16(h));
    __nv_bfloat162 l = __floats2bfloat162_rn(r0, r1);
    hi = *reinterpret_cast<uint32_t*>(&h);
    lo = *reinterpret_cast<uint32_t*>(&l);
}

// ---------------- split-transpose: in [Kd][Nd] fp32 -> out[n*ostride + k] bf16 hi/lo ----------------
__global__ void splitT_kernel(const float* __restrict__ in,
                              __nv_bfloat16* __restrict__ hi,
                              __nv_bfloat16* __restrict__ lo,
                              int Kd, int Nd, int ostride) {
    __shared__ float t[32][33];
    int n0 = blockIdx.x * 32, k0 = blockIdx.y * 32;
    int tx = threadIdx.x, ty = threadIdx.y;
#pragma unroll
    for (int j = 0; j < 4; j++)
        t[ty + j * 8][tx] = in[(size_t)(k0 + ty + j * 8) * Nd + n0 + tx];
    __syncthreads();
#pragma unroll
    for (int j = 0; j < 4; j++) {
        float v = t[tx][ty + j * 8];
        int n = n0 + ty + j * 8, k = k0 + tx;
        __nv_bfloat16 h = __float2bfloat16(v);
        hi[(size_t)n * ostride + k] = h;
        lo[(size_t)n * ostride + k] = __float2bfloat16(v - __bfloat162float(h));
    }
}

// ---------------- LayerNorm + split ----------------
__global__ void ln_split_kernel(const float* __restrict__ x,
                                const float* __restrict__ gamma,
                                const float* __restrict__ beta,
                                uint32_t* __restrict__ yh,
                                uint32_t* __restrict__ yl) {
    __shared__ float sh[8];
    __shared__ float stat;
    int row = blockIdx.x;
    int t = threadIdx.x;
    float4 xv = ((const float4*)(x + (size_t)row * D))[t];

    float s = xv.x + xv.y + xv.z + xv.w;
#pragma unroll
    for (int o = 16; o > 0; o >>= 1) s += __shfl_xor_sync(0xffffffffu, s, o);
    if ((t & 31) == 0) sh[t >> 5] = s;
    __syncthreads();
    if (t == 0) {
        float tot = 0.f;
#pragma unroll
        for (int i = 0; i < 8; i++) tot += sh[i];
        stat = tot * (1.f / (float)D);
    }
    __syncthreads();
    float mean = stat;

    float d0 = xv.x - mean, d1 = xv.y - mean, d2 = xv.z - mean, d3 = xv.w - mean;
    float sq = d0 * d0 + d1 * d1 + d2 * d2 + d3 * d3;
#pragma unroll
    for (int o = 16; o > 0; o >>= 1) sq += __shfl_xor_sync(0xffffffffu, sq, o);
    __syncthreads();
    if ((t & 31) == 0) sh[t >> 5] = sq;
    __syncthreads();
    if (t == 0) {
        float tot = 0.f;
#pragma unroll
        for (int i = 0; i < 8; i++) tot += sh[i];
        stat = rsqrtf(tot * (1.f / (float)D) + EPSF);
    }
    __syncthreads();
    float rinv = stat;

    float4 gv = ((const float4*)gamma)[t];
    float4 bv = ((const float4*)beta)[t];
    float v0 = d0 * rinv * gv.x + bv.x;
    float v1 = d1 * rinv * gv.y + bv.y;
    float v2 = d2 * rinv * gv.z + bv.z;
    float v3 = d3 * rinv * gv.w + bv.w;
    uint32_t h0, l0, h1, l1;
    packsplit(h0, l0, v0, v1);
    packsplit(h1, l1, v2, v3);
    int idx = row * (D / 2) + 2 * t;
    yh[idx] = h0; yh[idx + 1] = h1;
    yl[idx] = l0; yl[idx + 1] = l1;
}

// ---------------- per-head LN + scale + split ----------------
__global__ void qknorm_split(const float* __restrict__ tq, const float* __restrict__ scale,
                             uint32_t* __restrict__ oh, uint32_t* __restrict__ ol, float sc) {
    int row = blockIdx.x * blockDim.x + threadIdx.x;
    const float* p = tq + (size_t)row * DH;
    float4 v[16];
    float s = 0.f;
#pragma unroll
    for (int i = 0; i < 16; i++) {
        v[i] = ((const float4*)p)[i];
        s += v[i].x + v[i].y + v[i].z + v[i].w;
    }
    float mean = s * (1.f / (float)DH);
    float sq = 0.f;
#pragma unroll
    for (int i = 0; i < 16; i++) {
        v[i].x -= mean; v[i].y -= mean; v[i].z -= mean; v[i].w -= mean;
        sq += v[i].x * v[i].x + v[i].y * v[i].y + v[i].z * v[i].z + v[i].w * v[i].w;
    }
    float r = rsqrtf(sq * (1.f / (float)DH) + EPSF) * sc;
#pragma unroll
    for (int i = 0; i < 16; i++) {
        float4 scv = ((const float4*)scale)[i];
        uint32_t h0, l0, h1, l1;
        packsplit(h0, l0, v[i].x * r * scv.x, v[i].y * r * scv.y);
        packsplit(h1, l1, v[i].z * r * scv.z, v[i].w * r * scv.w);
        int idx = row * (DH / 2) + 2 * i;
        oh[idx] = h0; oh[idx + 1] = h1;
        ol[idx] = l0; ol[idx + 1] = l1;
    }
}

// ================= HMMA GEMM core (strided) =================
#define GBM 128
#define GBN 128
#define GBK 32
#define PLANE_B (128 * 40 * 2)
#define BUF_B   (4 * PLANE_B)
#define GSMEM   (2 * BUF_B)

__device__ __forceinline__ void issue_chunk(
    uint32_t base,
    const __nv_bfloat16* Ah, const __nv_bfloat16* Al,
    const __nv_bfloat16* Bh, const __nv_bfloat16* Bl,
    int bm, int bn, int kc, int lda, int ldb, int tid)
{
    int row  = tid >> 1;
    int half = tid & 1;
    uint32_t doff = row * 80 + half * 32;
    size_t aoff = (size_t)(bm + row) * lda + kc + half * 16;
    size_t boff = (size_t)(bn + row) * ldb + kc + half * 16;
    cp16(base + doff,                    Ah + aoff);
    cp16(base + doff + 16,               Ah + aoff + 8);
    cp16(base + PLANE_B + doff,          Al + aoff);
    cp16(base + PLANE_B + doff + 16,     Al + aoff + 8);
    cp16(base + 2 * PLANE_B + doff,      Bh + boff);
    cp16(base + 2 * PLANE_B + doff + 16, Bh + boff + 8);
    cp16(base + 3 * PLANE_B + doff,      Bl + boff);
    cp16(base + 3 * PLANE_B + doff + 16, Bl + boff + 8);
}

// mainloop: single barrier per chunk (top sync after wait orders buffer reuse)
__device__ __forceinline__ void hmma_mainloop(
    uint32_t sb, float acc[4][4][4],
    const __nv_bfloat16* Ah, const __nv_bfloat16* Al,
    const __nv_bfloat16* Bh, const __nv_bfloat16* Bl,
    int bm, int bn, int K, int lda, int ldb, int tid, int lane, int wm, int wn)
{
    uint32_t a_off = (uint32_t)((wm * 64 + (lane & 7) + (lane & 8)) * 80 + ((lane >> 4) << 4));
    uint32_t b_off = (uint32_t)((wn * 32 + (lane & 7)) * 80 + ((lane & 8) << 1));

    int nk = K / GBK;
    issue_chunk(sb, Ah, Al, Bh, Bl, bm, bn, 0, lda, ldb, tid);
    CP_COMMIT();

    for (int c = 0; c < nk; c++) {
        CP_WAIT0();
        __syncthreads();
        if (c + 1 < nk) {
            issue_chunk(sb + ((c + 1) & 1) * BUF_B, Ah, Al, Bh, Bl, bm, bn, (c + 1) * GBK, lda, ldb, tid);
            CP_COMMIT();
        }
        uint32_t base = sb + (c & 1) * BUF_B;
        uint32_t aH = base, aL = base + PLANE_B;
        uint32_t bH = base + 2 * PLANE_B, bL = base + 3 * PLANE_B;

#pragma unroll
        for (int k16 = 0; k16 < 2; k16++) {
            uint32_t kb = k16 * 32;
            uint32_t ahf[4][4], bfr[4][2];
#pragma unroll
            for (int mt = 0; mt < 4; mt++) ldmx4(ahf[mt], aH + a_off + mt * 1280 + kb);
#pragma unroll
            for (int nt = 0; nt < 4; nt++) ldmx2(bfr[nt], bH + b_off + nt * 640 + kb);
#pragma unroll
            for (int mt = 0; mt < 4; mt++)
#pragma unroll
                for (int nt = 0; nt < 4; nt++) mma16816(acc[mt][nt], ahf[mt], bfr[nt]);

            uint32_t alf[4][4];
#pragma unroll
            for (int mt = 0; mt < 4; mt++) ldmx4(alf[mt], aL + a_off + mt * 1280 + kb);
#pragma unroll
            for (int mt = 0; mt < 4; mt++)
#pragma unroll
                for (int nt = 0; nt < 4; nt++) mma16816(acc[mt][nt], alf[mt], bfr[nt]);

#pragma unroll
            for (int nt = 0; nt < 4; nt++) ldmx2(bfr[nt], bL + b_off + nt * 640 + kb);
#pragma unroll
            for (int mt = 0; mt < 4; mt++)
#pragma unroll
                for (int nt = 0; nt < 4; nt++) mma16816(acc[mt][nt], ahf[mt], bfr[nt]);
        }
        // no bottom sync: next iteration's top sync orders buffer reuse
    }
}

// ---- accumulate-GEMM body: C[,:N] += A @ B^T over K (strided) ----
__device__ __forceinline__ void gemm_acc_body(
    uint32_t sb, int bm, int bn,
    const __nv_bfloat16* Ah, const __nv_bfloat16* Al,
    const __nv_bfloat16* Bh, const __nv_bfloat16* Bl,
    int K, int lda, int ldb, float* C, int N, int tid, int lane, int wm, int wn)
{
    float acc[4][4][4];
#pragma unroll
    for (int i = 0; i < 4; i++)
#pragma unroll
        for (int j = 0; j < 4; j++)
#pragma unroll
            for (int r = 0; r < 4; r++) acc[i][j][r] = 0.f;

    hmma_mainloop(sb, acc, Ah, Al, Bh, Bl, bm, bn, K, lda, ldb, tid, lane, wm, wn);

    int lr = lane >> 2, lc = (lane & 3) * 2;
#pragma unroll
    for (int mt = 0; mt < 4; mt++) {
#pragma unroll
        for (int nt = 0; nt < 4; nt++) {
            float* a = acc[mt][nt];
            int m0 = bm + wm * 64 + mt * 16 + lr;
            int n0 = bn + wn * 32 + nt * 8 + lc;
            float2* p0 = (float2*)(C + (size_t)m0 * N + n0);
            float2* p1 = (float2*)(C + (size_t)(m0 + 8) * N + n0);
            float2 v0 = *p0, v1 = *p1;
            v0.x += a[0]; v0.y += a[1];
            v1.x += a[2]; v1.y += a[3];
            *p0 = v0; *p1 = v1;
        }
    }
}

// ---- fused GEMM 1: [xn] @ [w_in|wq|wk|wv]^T over N=7168 ----
__global__ void __launch_bounds__(256, 2) hmma_gemm_f1(
    const __nv_bfloat16* __restrict__ Ah, const __nv_bfloat16* __restrict__ Al,
    const __nv_bfloat16* __restrict__ Bh, const __nv_bfloat16* __restrict__ Bl,
    const float* __restrict__ b_in, const float* __restrict__ bq,
    const float* __restrict__ bk, const float* __restrict__ bv,
    uint32_t* __restrict__ acth, uint32_t* __restrict__ actl,
    float* __restrict__ qf, float* __restrict__ kf, float* __restrict__ vf)
{
    extern __shared__ __align__(128) char smem[];
    uint32_t sb = smem_u32(smem);
    int tid = threadIdx.x, lane = tid & 31, wid = tid >> 5;
    int wm = wid >> 2, wn = wid & 3;
    int bm = blockIdx.y * GBM, bn = blockIdx.x * GBN;

    float acc[4][4][4];
#pragma unroll
    for (int i = 0; i < 4; i++)
#pragma unroll
        for (int j = 0; j < 4; j++)
#pragma unroll
            for (int r = 0; r < 4; r++) acc[i][j][r] = 0.f;

    hmma_mainloop(sb, acc, Ah, Al, Bh, Bl, bm, bn, D, D, D, tid, lane, wm, wn);

    int lr = lane >> 2, lc = (lane & 3) * 2;
#pragma unroll
    for (int mt = 0; mt < 4; mt++) {
#pragma unroll
        for (int nt = 0; nt < 4; nt++) {
            float* a = acc[mt][nt];
            int m0 = bm + wm * 64 + mt * 16 + lr;
            int n0 = bn + wn * 32 + nt * 8 + lc;
            if (n0 < F) {
                float b0 = b_in[n0], b1 = b_in[n0 + 1];
                float v0 = gelu_f(a[0] + b0), v1 = gelu_f(a[1] + b1);
                float v2 = gelu_f(a[2] + b0), v3 = gelu_f(a[3] + b1);
                uint32_t h0, l0, h1, l1;
                packsplit(h0, l0, v0, v1);
                packsplit(h1, l1, v2, v3);
                size_t i0 = (size_t)m0 * (K2 / 2) + (n0 >> 1);
                size_t i1 = (size_t)(m0 + 8) * (K2 / 2) + (n0 >> 1);
                acth[i0] = h0; actl[i0] = l0;
                acth[i1] = h1; actl[i1] = l1;
            } else {
                int r = (n0 - F) >> 10;
                int c = (n0 - F) & (D - 1);
                const float* bp = (r == 0) ? bq : (r == 1) ? bk : bv;
                float* dst = (r == 0) ? qf : (r == 1) ? kf : vf;
                float b0 = bp[c], b1 = bp[c + 1];
                float2 w0 = {a[0] + b0, a[1] + b1};
                float2 w1 = {a[2] + b0, a[3] + b1};
                *(float2*)(dst + (size_t)m0 * D + c) = w0;
                *(float2*)(dst + (size_t)(m0 + 8) * D + c) = w1;
            }
        }
    }
}

// ---- standalone accumulate GEMM (for the o @ w_ao tail) ----
__global__ void __launch_bounds__(256, 2) hmma_gemm_acc(
    const __nv_bfloat16* __restrict__ Ah, const __nv_bfloat16* __restrict__ Al,
    const __nv_bfloat16* __restrict__ Bh, const __nv_bfloat16* __restrict__ Bl,
    float* __restrict__ C, int N, int K, int lda, int ldb)
{
    extern __shared__ __align__(128) char smem[];
    uint32_t sb = smem_u32(smem);
    int tid = threadIdx.x, lane = tid & 31, wid = tid >> 5;
    gemm_acc_body(sb, blockIdx.y * GBM, blockIdx.x * GBN, Ah, Al, Bh, Bl,
                  K, lda, ldb, C, N, tid, lane, wid >> 2, wid & 3);
}

// ================= attention body (device) =================
#define AT_STRIDE 144
#define AT_PLANE (64 * AT_STRIDE)
#define AT_BUF   (4 * AT_PLANE)

__device__ __forceinline__ void at_load_tile(
    uint32_t dst, const __nv_bfloat16* kh, const __nv_bfloat16* kl,
    const __nv_bfloat16* vth, const __nv_bfloat16* vtl,
    int head, int kt, int tid)
{
    int row = tid >> 2, q4 = tid & 3;
    size_t koff = (size_t)(kt * 64 + row) * D + head * DH + q4 * 16;
    uint32_t d = dst + row * AT_STRIDE + q4 * 32;
    cp16(d,                    kh + koff);
    cp16(d + 16,               kh + koff + 8);
    cp16(d + AT_PLANE,         kl + koff);
    cp16(d + AT_PLANE + 16,    kl + koff + 8);
    size_t voff = (size_t)(head * DH + row) * S + kt * 64 + q4 * 16;
    cp16(d + 2 * AT_PLANE,      vth + voff);
    cp16(d + 2 * AT_PLANE + 16, vth + voff + 8);
    cp16(d + 3 * AT_PLANE,      vtl + voff);
    cp16(d + 3 * AT_PLANE + 16, vtl + voff + 8);
}

__device__ void attn_body(
    uint32_t sb, int qt, int head,
    const __nv_bfloat16* qh, const __nv_bfloat16* ql,
    const __nv_bfloat16* kh, const __nv_bfloat16* kl,
    const __nv_bfloat16* vth, const __nv_bfloat16* vtl,
    uint32_t* acth, uint32_t* actl)
{
    int tid = threadIdx.x, lane = tid & 31, wid = tid >> 5;
    int ntiles = 2 * qt + 2;

    {
        int row = tid >> 1, half = tid & 1;
        const __nv_bfloat16* s0 = qh + (size_t)(qt * 128 + row) * D + head * DH + half * 32;
        const __nv_bfloat16* s1 = ql + (size_t)(qt * 128 + row) * D + head * DH + half * 32;
        uint32_t dq = sb + AT_BUF + row * AT_STRIDE + half * 64;
        cp16(dq,      s0); cp16(dq + 16, s0 + 8);
        cp16(dq + 32, s0 + 16); cp16(dq + 48, s0 + 24);
        uint32_t dl = dq + 2 * AT_PLANE;
        cp16(dl,      s1); cp16(dl + 16, s1 + 8);
        cp16(dl + 32, s1 + 16); cp16(dl + 48, s1 + 24);
    }
    CP_COMMIT();
    at_load_tile(sb, kh, kl, vth, vtl, head, 0, tid);
    CP_COMMIT();
    CP_WAIT0();
    __syncthreads();

    uint32_t qhf[4][4], qlf[4][4];
#pragma unroll
    for (int kc = 0; kc < 4; kc++) {
        uint32_t a = sb + AT_BUF + (wid * 16 + (lane & 15)) * AT_STRIDE
                   + ((lane >> 4) & 1) * 16 + kc * 32;
        ldmx4(qhf[kc], a);
        ldmx4(qlf[kc], a + 2 * AT_PLANE);
    }
    __syncthreads();
    if (ntiles > 1) { at_load_tile(sb + AT_BUF, kh, kl, vth, vtl, head, 1, tid); CP_COMMIT(); }

    float oacc[8][4];
#pragma unroll
    for (int i = 0; i < 8; i++)
#pragma unroll
        for (int j = 0; j < 4; j++) oacc[i][j] = 0.f;
    float m0 = -INFINITY, m1 = -INFINITY, l0 = 0.f, l1 = 0.f;
    int row0 = qt * 128 + wid * 16 + (lane >> 2);

    for (int kt = 0; kt < ntiles; kt++) {
        if (kt + 1 < ntiles) CP_WAIT1(); else CP_WAIT0();
        __syncthreads();
        uint32_t base = sb + (kt & 1) * AT_BUF;

        if (kt * 64 <= qt * 128 + wid * 16 + 15) {
            float s[8][4];
#pragma unroll
            for (int i = 0; i < 8; i++)
#pragma unroll
                for (int j = 0; j < 4; j++) s[i][j] = 0.f;

#pragma unroll
            for (int kc = 0; kc < 4; kc++) {
                uint32_t koff = ((lane & 8) << 1) + kc * 32;
#pragma unroll
                for (int nt = 0; nt < 8; nt++) {
                    uint32_t ka = base + (nt * 8 + (lane & 7)) * AT_STRIDE + koff;
                    uint32_t bh[2], bl[2];
                    ldmx2(bh, ka);
                    ldmx2(bl, ka + AT_PLANE);
                    mma16816(s[nt], qhf[kc], bh);
                    mma16816(s[nt], qhf[kc], bl);
                    mma16816(s[nt], qlf[kc], bh);
                }
            }

            if (kt >= 2 * qt) {
#pragma unroll
                for (int nt = 0; nt < 8; nt++) {
                    int c = kt * 64 + nt * 8 + 2 * (lane & 3);
                    if (c     > row0)     s[nt][0] = -INFINITY;
                    if (c + 1 > row0)     s[nt][1] = -INFINITY;
                    if (c     > row0 + 8) s[nt][2] = -INFINITY;
                    if (c + 1 > row0 + 8) s[nt][3] = -INFINITY;
                }
            }

            float mx0 = -INFINITY, mx1 = -INFINITY;
#pragma unroll
            for (int nt = 0; nt < 8; nt++) {
                mx0 = fmaxf(mx0, fmaxf(s[nt][0], s[nt][1]));
                mx1 = fmaxf(mx1, fmaxf(s[nt][2], s[nt][3]));
            }
            mx0 = fmaxf(mx0, __shfl_xor_sync(0xffffffffu, mx0, 1));
            mx0 = fmaxf(mx0, __shfl_xor_sync(0xffffffffu, mx0, 2));
            mx1 = fmaxf(mx1, __shfl_xor_sync(0xffffffffu, mx1, 1));
            mx1 = fmaxf(mx1, __shfl_xor_sync(0xffffffffu, mx1, 2));
            float nm0 = fmaxf(m0, mx0), nm1 = fmaxf(m1, mx1);
            float a0 = __expf(m0 - nm0), a1 = __expf(m1 - nm1);
            m0 = nm0; m1 = nm1;
            float ps0 = 0.f, ps1 = 0.f;
#pragma unroll
            for (int nt = 0; nt < 8; nt++) {
                s[nt][0] = __expf(s[nt][0] - m0); ps0 += s[nt][0];
                s[nt][1] = __expf(s[nt][1] - m0); ps0 += s[nt][1];
                s[nt][2] = __expf(s[nt][2] - m1); ps1 += s[nt][2];
                s[nt][3] = __expf(s[nt][3] - m1); ps1 += s[nt][3];
            }
            l0 = l0 * a0 + ps0;
            l1 = l1 * a1 + ps1;
#pragma unroll
            for (int dt = 0; dt < 8; dt++) {
                oacc[dt][0] *= a0; oacc[dt][1] *= a0;
                oacc[dt][2] *= a1; oacc[dt][3] *= a1;
            }

#pragma unroll
            for (int kc = 0; kc < 4; kc++) {
                uint32_t ph[4], pl[4];
                packsplit(ph[0], pl[0], s[2 * kc][0],     s[2 * kc][1]);
                packsplit(ph[1], pl[1], s[2 * kc][2],     s[2 * kc][3]);
                packsplit(ph[2], pl[2], s[2 * kc + 1][0], s[2 * kc + 1][1]);
                packsplit(ph[3], pl[3], s[2 * kc + 1][2], s[2 * kc + 1][3]);
                uint32_t koff = ((lane & 8) << 1) + kc * 32;
#pragma unroll
                for (int dt = 0; dt < 8; dt++) {
                    uint32_t va = base + 2 * AT_PLANE + (dt * 8 + (lane & 7)) * AT_STRIDE + koff;
                    uint32_t vh[2], vl[2];
                    ldmx2(vh, va);
                    ldmx2(vl, va + AT_PLANE);
                    mma16816(oacc[dt], ph, vh);
                    mma16816(oacc[dt], ph, vl);
                    mma16816(oacc[dt], pl, vh);
                }
            }
        }
        __syncthreads();
        if (kt + 2 < ntiles) { at_load_tile(base, kh, kl, vth, vtl, head, kt + 2, tid); CP_COMMIT(); }
    }

    l0 += __shfl_xor_sync(0xffffffffu, l0, 1);
    l0 += __shfl_xor_sync(0xffffffffu, l0, 2);
    l1 += __shfl_xor_sync(0xffffffffu, l1, 1);
    l1 += __shfl_xor_sync(0xffffffffu, l1, 2);
    float i0 = 1.f / l0, i1 = 1.f / l1;
#pragma unroll
    for (int dt = 0; dt < 8; dt++) {
        int col = F + head * DH + dt * 8 + 2 * (lane & 3);
        uint32_t h0, lo0, h1, lo1;
        packsplit(h0, lo0, oacc[dt][0] * i0, oacc[dt][1] * i0);
        packsplit(h1, lo1, oacc[dt][2] * i1, oacc[dt][3] * i1);
        size_t i0x = (size_t)row0 * (K2 / 2) + (col >> 1);
        size_t i1x = (size_t)(row0 + 8) * (K2 / 2) + (col >> 1);
        acth[i0x] = h0; actl[i0x] = lo0;
        acth[i1x] = h1; actl[i1x] = lo1;
    }
}

// ================= fat kernel: attention (512 CTAs) + out += h@w_mo (256 CTAs) =================
// bid = 3t+r: r in {0,1} -> attention idx 2t+r; r==2 -> gemm idx t. 2:1 interleave
// keeps every SM co-resident with one GEMM CTA and one attention CTA.
__global__ void __launch_bounds__(256, 2) fused_tail(
    const __nv_bfloat16* __restrict__ qh, const __nv_bfloat16* __restrict__ ql,
    const __nv_bfloat16* __restrict__ kh, const __nv_bfloat16* __restrict__ kl,
    const __nv_bfloat16* __restrict__ vth, const __nv_bfloat16* __restrict__ vtl,
    uint32_t* __restrict__ acth_w, uint32_t* __restrict__ actl_w,
    const __nv_bfloat16* __restrict__ acth_r, const __nv_bfloat16* __restrict__ actl_r,
    const __nv_bfloat16* __restrict__ w2h, const __nv_bfloat16* __restrict__ w2l,
    float* __restrict__ out)
{
    extern __shared__ __align__(128) char smem[];
    uint32_t sb = smem_u32(smem);
    int bid = blockIdx.x;
    int t3 = bid / 3, r3 = bid - 3 * t3;

    if (r3 == 2) {
        // GEMM part: out += h @ w_mo  (K window [0, 4096))
        int tid = threadIdx.x, lane = tid & 31, wid = tid >> 5;
        int bm = (t3 >> 3) * GBM, bn = (t3 & 7) * GBN;
        gemm_acc_body(sb, bm, bn, acth_r, actl_r, w2h, w2l,
                      F, K2, K2, out, D, tid, lane, wid >> 2, wid & 3);
    } else {
        int a = 2 * t3 + r3;                 // 0..511, heavy tiles first
        int qt = 31 - (a >> 4);
        int head = a & 15;
        attn_body(sb, qt, head, qh, ql, kh, kl, vth, vtl, acth_w, actl_w);
    }
}

// ---------------- out = x + b_mo + b_ao ----------------
__global__ void init_out_kernel(const float* __restrict__ x,
                                const float* __restrict__ bmo,
                                const float* __restrict__ bao,
                                float* __restrict__ out) {
    int i = blockIdx.x * blockDim.x + threadIdx.x;
    int col = i & (D - 1);
    out[i] = x[i] + bmo[col] + bao[col];
}

// ---------------- launch ----------------
extern "C" void kernel_launch(void* const* d_in, const int* in_sizes, int n_in,
                              void* d_out, int out_size) {
    const float* x        = (const float*)d_in[0];
    // d_in[1] = mask (causal tril) handled analytically
    const float* ln_scale = (const float*)d_in[2];
    const float* ln_bias  = (const float*)d_in[3];
    const float* w_in     = (const float*)d_in[4];
    const float* b_in     = (const float*)d_in[5];
    const float* wq       = (const float*)d_in[6];
    const float* bq       = (const float*)d_in[7];
    const float* wk       = (const float*)d_in[8];
    const float* bk       = (const float*)d_in[9];
    const float* wv       = (const float*)d_in[10];
    const float* bv       = (const float*)d_in[11];
    const float* qn       = (const float*)d_in[12];
    const float* kn       = (const float*)d_in[13];
    const float* w_mo     = (const float*)d_in[14];
    const float* b_mo     = (const float*)d_in[15];
    const float* w_ao     = (const float*)d_in[16];
    const float* b_ao     = (const float*)d_in[17];
    float* out = (float*)d_out;

    float *q, *k, *v;
    cudaGetSymbolAddress((void**)&q, g_q);
    cudaGetSymbolAddress((void**)&k, g_k);
    cudaGetSymbolAddress((void**)&v, g_v);

    __nv_bfloat16 *xnh, *xnl, *acth, *actl, *qsh, *qsl, *ksh, *ksl, *vth, *vtl;
    __nv_bfloat16 *w1h, *w1l, *w2h, *w2l;
    cudaGetSymbolAddress((void**)&xnh, g_xnh);   cudaGetSymbolAddress((void**)&xnl, g_xnl);
    cudaGetSymbolAddress((void**)&acth, g_acth); cudaGetSymbolAddress((void**)&actl, g_actl);
    cudaGetSymbolAddress((void**)&qsh, g_qsh);   cudaGetSymbolAddress((void**)&qsl, g_qsl);
    cudaGetSymbolAddress((void**)&ksh, g_ksh);   cudaGetSymbolAddress((void**)&ksl, g_ksl);
    cudaGetSymbolAddress((void**)&vth, g_vth);   cudaGetSymbolAddress((void**)&vtl, g_vtl);
    cudaGetSymbolAddress((void**)&w1h, g_w1h);   cudaGetSymbolAddress((void**)&w1l, g_w1l);
    cudaGetSymbolAddress((void**)&w2h, g_w2h);   cudaGetSymbolAddress((void**)&w2l, g_w2l);

    cudaFuncSetAttribute(hmma_gemm_f1,  cudaFuncAttributeMaxDynamicSharedMemorySize, GSMEM);
    cudaFuncSetAttribute(hmma_gemm_acc, cudaFuncAttributeMaxDynamicSharedMemorySize, GSMEM);
    cudaFuncSetAttribute(fused_tail,    cudaFuncAttributeMaxDynamicSharedMemorySize, GSMEM);

    // ---- weight packing
    splitT_kernel<<<dim3(F / 32, D / 32), dim3(32, 8)>>>(w_in, w1h, w1l, D, F, D);
    splitT_kernel<<<dim3(D / 32, D / 32), dim3(32, 8)>>>(wq, w1h + (size_t)F * D, w1l + (size_t)F * D, D, D, D);
    splitT_kernel<<<dim3(D / 32, D / 32), dim3(32, 8)>>>(wk, w1h + (size_t)(F + D) * D, w1l + (size_t)(F + D) * D, D, D, D);
    splitT_kernel<<<dim3(D / 32, D / 32), dim3(32, 8)>>>(wv, w1h + (size_t)(F + 2 * D) * D, w1l + (size_t)(F + 2 * D) * D, D, D, D);
    splitT_kernel<<<dim3(D / 32, F / 32), dim3(32, 8)>>>(w_mo, w2h, w2l, F, D, K2);
    splitT_kernel<<<dim3(D / 32, D / 32), dim3(32, 8)>>>(w_ao, w2h + F, w2l + F, D, D, K2);

    // 1. PreNorm (split planes)
    ln_split_kernel<<<S, 256>>>(x, ln_scale, ln_bias, (uint32_t*)xnh, (uint32_t*)xnl);

    // 2. fused MLP-in(+GELU+split) & QKV GEMM
    hmma_gemm_f1<<<dim3(N1 / 128, S / 128), 256, GSMEM>>>(
        xnh, xnl, w1h, w1l, b_in, bq, bk, bv,
        (uint32_t*)acth, (uint32_t*)actl, q, k, v);

    // 3. qk-norm + split; V split-transpose; out init
    qknorm_split<<<(S * H) / 256, 256>>>(q, qn, (uint32_t*)qsh, (uint32_t*)qsl, 0.125f);
    qknorm_split<<<(S * H) / 256, 256>>>(k, kn, (uint32_t*)ksh, (uint32_t*)ksl, 1.f);
    splitT_kernel<<<dim3(D / 32, S / 32), dim3(32, 8)>>>(v, vth, vtl, S, D, S);
    init_out_kernel<<<(S * D) / 256, 256>>>(x, b_mo, b_ao, out);

    // 4. fat kernel: attention (writes act[:,4096:]) + out += h@w_mo, co-resident
    fused_tail<<<768, 256, GSMEM>>>(qsh, qsl, ksh, ksl, vth, vtl,
                                    (uint32_t*)acth, (uint32_t*)actl,
                                    acth, actl, w2h, w2l, out);

    // 5. out += o @ w_ao (K window [4096, 5120))
    hmma_gemm_acc<<<dim3(D / 128, S / 128), 256, GSMEM>>>(
        acth + F, actl + F, w2h + F, w2l + F, out, D, D, K2, K2);
}

// round 9
// speedup vs baseline: 1.0913x; 1.0913x over previous
#include <cuda_runtime.h>
#include <cuda_bf16.h>
#include <math.h>
#include <stdint.h>

#define S 4096
#define D 1024
#define H 16
#define DH 64
#define F 4096
#define N1 7168              // F + 3*D : fused MLP-in + QKV output width
#define K2 5120              // F + D   : packed activation width [h | o]
#define EPSF 1e-6f

// ---------------- scratch (device globals: alloc-free) ----------------
__device__ float g_q [S * D];
__device__ float g_k [S * D];
__device__ float g_v [S * D];

__device__ __nv_bfloat16 g_xnh[S * D], g_xnl[S * D];       // LN output planes
__device__ __nv_bfloat16 g_acth[S * K2], g_actl[S * K2];   // [h | o] planes, stride K2
__device__ __nv_bfloat16 g_qsh[S * D], g_qsl[S * D];       // q * 1/8 planes
__device__ __nv_bfloat16 g_ksh[S * D], g_ksl[S * D];       // k planes
__device__ __nv_bfloat16 g_vth[D * S], g_vtl[D * S];       // V^T planes [H*64 dims][S keys]
__device__ __nv_bfloat16 g_w1h[N1 * D], g_w1l[N1 * D];     // [w_in|wq|wk|wv]^T  [7168][1024]
__device__ __nv_bfloat16 g_w2h[D * K2], g_w2l[D * K2];     // [w_mo;w_ao]^T      [1024][5120]

// ---------------- small asm helpers (base sm_103 instructions) ----------------
__device__ __forceinline__ uint32_t smem_u32(const void* p) {
    uint32_t a;
    asm("{ .reg .u64 t; cvta.to.shared.u64 t, %1; cvt.u32.u64 %0, t; }" : "=r"(a) : "l"(p));
    return a;
}
__device__ __forceinline__ void cp16(uint32_t d, const void* s) {
    asm volatile("cp.async.cg.shared.global [%0], [%1], 16;" :: "r"(d), "l"(s));
}
#define CP_COMMIT() asm volatile("cp.async.commit_group;" ::: "memory")
#define CP_WAIT1()  asm volatile("cp.async.wait_group 1;" ::: "memory")
#define CP_WAIT0()  asm volatile("cp.async.wait_group 0;" ::: "memory")

__device__ __forceinline__ void ldmx4(uint32_t* r, uint32_t a) {
    asm volatile("ldmatrix.sync.aligned.m8n8.x4.shared.b16 {%0,%1,%2,%3}, [%4];"
                 : "=r"(r[0]), "=r"(r[1]), "=r"(r[2]), "=r"(r[3]) : "r"(a));
}
__device__ __forceinline__ void ldmx2(uint32_t* r, uint32_t a) {
    asm volatile("ldmatrix.sync.aligned.m8n8.x2.shared.b16 {%0,%1}, [%2];"
                 : "=r"(r[0]), "=r"(r[1]) : "r"(a));
}
__device__ __forceinline__ void mma16816(float* c, const uint32_t* a, const uint32_t* b) {
    asm volatile("mma.sync.aligned.m16n8k16.row.col.f32.bf16.bf16.f32 "
                 "{%0,%1,%2,%3}, {%4,%5,%6,%7}, {%8,%9}, {%0,%1,%2,%3};"
                 : "+f"(c[0]), "+f"(c[1]), "+f"(c[2]), "+f"(c[3])
                 : "r"(a[0]), "r"(a[1]), "r"(a[2]), "r"(a[3]), "r"(b[0]), "r"(b[1]));
}

__device__ __forceinline__ float gelu_f(float x) {
    float x3 = x * x * x;
    return 0.5f * x * (1.f + tanhf(0.7978845608028654f * (x + 0.044715f * x3)));
}

__device__ __forceinline__ void packsplit(uint32_t& hi, uint32_t& lo, float a, float b) {
    __nv_bfloat162 h = __floats2bfloat162_rn(a, b);
    float r0 = a - __bfloat162float(__low2bfloat16(h));
    float r1 = b - __bfloat162float(__high2bfloat16(h));
    __nv_bfloat162 l = __floats2bfloat162_rn(r0, r1);
    hi = *reinterpret_cast<uint32_t*>(&h);
    lo = *reinterpret_cast<uint32_t*>(&l);
}

// ---------------- split-transpose: in [Kd][Nd] fp32 -> out[n*ostride + k] bf16 hi/lo ----------------
__global__ void splitT_kernel(const float* __restrict__ in,
                              __nv_bfloat16* __restrict__ hi,
                              __nv_bfloat16* __restrict__ lo,
                              int Kd, int Nd, int ostride) {
    __shared__ float t[32][33];
    int n0 = blockIdx.x * 32, k0 = blockIdx.y * 32;
    int tx = threadIdx.x, ty = threadIdx.y;
#pragma unroll
    for (int j = 0; j < 4; j++)
        t[ty + j * 8][tx] = in[(size_t)(k0 + ty + j * 8) * Nd + n0 + tx];
    __syncthreads();
#pragma unroll
    for (int j = 0; j < 4; j++) {
        float v = t[tx][ty + j * 8];
        int n = n0 + ty + j * 8, k = k0 + tx;
        __nv_bfloat16 h = __float2bfloat16(v);
        hi[(size_t)n * ostride + k] = h;
        lo[(size_t)n * ostride + k] = __float2bfloat16(v - __bfloat162float(h));
    }
}

// ---------------- LayerNorm + split ----------------
__global__ void ln_split_kernel(const float* __restrict__ x,
                                const float* __restrict__ gamma,
                                const float* __restrict__ beta,
                                uint32_t* __restrict__ yh,
                                uint32_t* __restrict__ yl) {
    __shared__ float sh[8];
    __shared__ float stat;
    int row = blockIdx.x;
    int t = threadIdx.x;
    float4 xv = ((const float4*)(x + (size_t)row * D))[t];

    float s = xv.x + xv.y + xv.z + xv.w;
#pragma unroll
    for (int o = 16; o > 0; o >>= 1) s += __shfl_xor_sync(0xffffffffu, s, o);
    if ((t & 31) == 0) sh[t >> 5] = s;
    __syncthreads();
    if (t == 0) {
        float tot = 0.f;
#pragma unroll
        for (int i = 0; i < 8; i++) tot += sh[i];
        stat = tot * (1.f / (float)D);
    }
    __syncthreads();
    float mean = stat;

    float d0 = xv.x - mean, d1 = xv.y - mean, d2 = xv.z - mean, d3 = xv.w - mean;
    float sq = d0 * d0 + d1 * d1 + d2 * d2 + d3 * d3;
#pragma unroll
    for (int o = 16; o > 0; o >>= 1) sq += __shfl_xor_sync(0xffffffffu, sq, o);
    __syncthreads();
    if ((t & 31) == 0) sh[t >> 5] = sq;
    __syncthreads();
    if (t == 0) {
        float tot = 0.f;
#pragma unroll
        for (int i = 0; i < 8; i++) tot += sh[i];
        stat = rsqrtf(tot * (1.f / (float)D) + EPSF);
    }
    __syncthreads();
    float rinv = stat;

    float4 gv = ((const float4*)gamma)[t];
    float4 bv = ((const float4*)beta)[t];
    float v0 = d0 * rinv * gv.x + bv.x;
    float v1 = d1 * rinv * gv.y + bv.y;
    float v2 = d2 * rinv * gv.z + bv.z;
    float v3 = d3 * rinv * gv.w + bv.w;
    uint32_t h0, l0, h1, l1;
    packsplit(h0, l0, v0, v1);
    packsplit(h1, l1, v2, v3);
    int idx = row * (D / 2) + 2 * t;
    yh[idx] = h0; yh[idx + 1] = h1;
    yl[idx] = l0; yl[idx + 1] = l1;
}

// ---------------- per-head LN + scale + split ----------------
__global__ void qknorm_split(const float* __restrict__ tq, const float* __restrict__ scale,
                             uint32_t* __restrict__ oh, uint32_t* __restrict__ ol, float sc) {
    int row = blockIdx.x * blockDim.x + threadIdx.x;
    const float* p = tq + (size_t)row * DH;
    float4 v[16];
    float s = 0.f;
#pragma unroll
    for (int i = 0; i < 16; i++) {
        v[i] = ((const float4*)p)[i];
        s += v[i].x + v[i].y + v[i].z + v[i].w;
    }
    float mean = s * (1.f / (float)DH);
    float sq = 0.f;
#pragma unroll
    for (int i = 0; i < 16; i++) {
        v[i].x -= mean; v[i].y -= mean; v[i].z -= mean; v[i].w -= mean;
        sq += v[i].x * v[i].x + v[i].y * v[i].y + v[i].z * v[i].z + v[i].w * v[i].w;
    }
    float r = rsqrtf(sq * (1.f / (float)DH) + EPSF) * sc;
#pragma unroll
    for (int i = 0; i < 16; i++) {
        float4 scv = ((const float4*)scale)[i];
        uint32_t h0, l0, h1, l1;
        packsplit(h0, l0, v[i].x * r * scv.x, v[i].y * r * scv.y);
        packsplit(h1, l1, v[i].z * r * scv.z, v[i].w * r * scv.w);
        int idx = row * (DH / 2) + 2 * i;
        oh[idx] = h0; oh[idx + 1] = h1;
        ol[idx] = l0; ol[idx + 1] = l1;
    }
}

// ================= HMMA GEMM core (strided) =================
#define GBM 128
#define GBN 128
#define GBK 32
#define PLANE_B (128 * 40 * 2)
#define BUF_B   (4 * PLANE_B)
#define GSMEM   (2 * BUF_B)

__device__ __forceinline__ void issue_chunk(
    uint32_t base,
    const __nv_bfloat16* Ah, const __nv_bfloat16* Al,
    const __nv_bfloat16* Bh, const __nv_bfloat16* Bl,
    int bm, int bn, int kc, int lda, int ldb, int tid)
{
    int row  = tid >> 1;
    int half = tid & 1;
    uint32_t doff = row * 80 + half * 32;
    size_t aoff = (size_t)(bm + row) * lda + kc + half * 16;
    size_t boff = (size_t)(bn + row) * ldb + kc + half * 16;
    cp16(base + doff,                    Ah + aoff);
    cp16(base + doff + 16,               Ah + aoff + 8);
    cp16(base + PLANE_B + doff,          Al + aoff);
    cp16(base + PLANE_B + doff + 16,     Al + aoff + 8);
    cp16(base + 2 * PLANE_B + doff,      Bh + boff);
    cp16(base + 2 * PLANE_B + doff + 16, Bh + boff + 8);
    cp16(base + 3 * PLANE_B + doff,      Bl + boff);
    cp16(base + 3 * PLANE_B + doff + 16, Bl + boff + 8);
}

// mainloop: single barrier per chunk (top sync after wait orders buffer reuse)
__device__ __forceinline__ void hmma_mainloop(
    uint32_t sb, float acc[4][4][4],
    const __nv_bfloat16* Ah, const __nv_bfloat16* Al,
    const __nv_bfloat16* Bh, const __nv_bfloat16* Bl,
    int bm, int bn, int K, int lda, int ldb, int tid, int lane, int wm, int wn)
{
    uint32_t a_off = (uint32_t)((wm * 64 + (lane & 7) + (lane & 8)) * 80 + ((lane >> 4) << 4));
    uint32_t b_off = (uint32_t)((wn * 32 + (lane & 7)) * 80 + ((lane & 8) << 1));

    int nk = K / GBK;
    issue_chunk(sb, Ah, Al, Bh, Bl, bm, bn, 0, lda, ldb, tid);
    CP_COMMIT();

    for (int c = 0; c < nk; c++) {
        CP_WAIT0();
        __syncthreads();
        if (c + 1 < nk) {
            issue_chunk(sb + ((c + 1) & 1) * BUF_B, Ah, Al, Bh, Bl, bm, bn, (c + 1) * GBK, lda, ldb, tid);
            CP_COMMIT();
        }
        uint32_t base = sb + (c & 1) * BUF_B;
        uint32_t aH = base, aL = base + PLANE_B;
        uint32_t bH = base + 2 * PLANE_B, bL = base + 3 * PLANE_B;

#pragma unroll
        for (int k16 = 0; k16 < 2; k16++) {
            uint32_t kb = k16 * 32;
            uint32_t ahf[4][4], bfr[4][2];
#pragma unroll
            for (int mt = 0; mt < 4; mt++) ldmx4(ahf[mt], aH + a_off + mt * 1280 + kb);
#pragma unroll
            for (int nt = 0; nt < 4; nt++) ldmx2(bfr[nt], bH + b_off + nt * 640 + kb);
#pragma unroll
            for (int mt = 0; mt < 4; mt++)
#pragma unroll
                for (int nt = 0; nt < 4; nt++) mma16816(acc[mt][nt], ahf[mt], bfr[nt]);

            uint32_t alf[4][4];
#pragma unroll
            for (int mt = 0; mt < 4; mt++) ldmx4(alf[mt], aL + a_off + mt * 1280 + kb);
#pragma unroll
            for (int mt = 0; mt < 4; mt++)
#pragma unroll
                for (int nt = 0; nt < 4; nt++) mma16816(acc[mt][nt], alf[mt], bfr[nt]);

#pragma unroll
            for (int nt = 0; nt < 4; nt++) ldmx2(bfr[nt], bL + b_off + nt * 640 + kb);
#pragma unroll
            for (int mt = 0; mt < 4; mt++)
#pragma unroll
                for (int nt = 0; nt < 4; nt++) mma16816(acc[mt][nt], ahf[mt], bfr[nt]);
        }
    }
}

// ---- fused GEMM 1: [xn] @ [w_in|wq|wk|wv]^T over N=7168 ----
__global__ void __launch_bounds__(256, 2) hmma_gemm_f1(
    const __nv_bfloat16* __restrict__ Ah, const __nv_bfloat16* __restrict__ Al,
    const __nv_bfloat16* __restrict__ Bh, const __nv_bfloat16* __restrict__ Bl,
    const float* __restrict__ b_in, const float* __restrict__ bq,
    const float* __restrict__ bk, const float* __restrict__ bv,
    uint32_t* __restrict__ acth, uint32_t* __restrict__ actl,
    float* __restrict__ qf, float* __restrict__ kf, float* __restrict__ vf)
{
    extern __shared__ __align__(128) char smem[];
    uint32_t sb = smem_u32(smem);
    int tid = threadIdx.x, lane = tid & 31, wid = tid >> 5;
    int wm = wid >> 2, wn = wid & 3;
    int bm = blockIdx.y * GBM, bn = blockIdx.x * GBN;

    float acc[4][4][4];
#pragma unroll
    for (int i = 0; i < 4; i++)
#pragma unroll
        for (int j = 0; j < 4; j++)
#pragma unroll
            for (int r = 0; r < 4; r++) acc[i][j][r] = 0.f;

    hmma_mainloop(sb, acc, Ah, Al, Bh, Bl, bm, bn, D, D, D, tid, lane, wm, wn);

    int lr = lane >> 2, lc = (lane & 3) * 2;
#pragma unroll
    for (int mt = 0; mt < 4; mt++) {
#pragma unroll
        for (int nt = 0; nt < 4; nt++) {
            float* a = acc[mt][nt];
            int m0 = bm + wm * 64 + mt * 16 + lr;
            int n0 = bn + wn * 32 + nt * 8 + lc;
            if (n0 < F) {
                float b0 = b_in[n0], b1 = b_in[n0 + 1];
                float v0 = gelu_f(a[0] + b0), v1 = gelu_f(a[1] + b1);
                float v2 = gelu_f(a[2] + b0), v3 = gelu_f(a[3] + b1);
                uint32_t h0, l0, h1, l1;
                packsplit(h0, l0, v0, v1);
                packsplit(h1, l1, v2, v3);
                size_t i0 = (size_t)m0 * (K2 / 2) + (n0 >> 1);
                size_t i1 = (size_t)(m0 + 8) * (K2 / 2) + (n0 >> 1);
                acth[i0] = h0; actl[i0] = l0;
                acth[i1] = h1; actl[i1] = l1;
            } else {
                int r = (n0 - F) >> 10;
                int c = (n0 - F) & (D - 1);
                const float* bp = (r == 0) ? bq : (r == 1) ? bk : bv;
                float* dst = (r == 0) ? qf : (r == 1) ? kf : vf;
                float b0 = bp[c], b1 = bp[c + 1];
                float2 w0 = {a[0] + b0, a[1] + b1};
                float2 w1 = {a[2] + b0, a[3] + b1};
                *(float2*)(dst + (size_t)m0 * D + c) = w0;
                *(float2*)(dst + (size_t)(m0 + 8) * D + c) = w1;
            }
        }
    }
}

// ---- accumulate GEMM: C += A @ B^T over K window (strided) ----
__global__ void __launch_bounds__(256, 2) hmma_gemm_acc(
    const __nv_bfloat16* __restrict__ Ah, const __nv_bfloat16* __restrict__ Al,
    const __nv_bfloat16* __restrict__ Bh, const __nv_bfloat16* __restrict__ Bl,
    float* __restrict__ C, int N, int K, int lda, int ldb)
{
    extern __shared__ __align__(128) char smem[];
    uint32_t sb = smem_u32(smem);
    int tid = threadIdx.x, lane = tid & 31, wid = tid >> 5;
    int wm = wid >> 2, wn = wid & 3;
    int bm = blockIdx.y * GBM, bn = blockIdx.x * GBN;

    float acc[4][4][4];
#pragma unroll
    for (int i = 0; i < 4; i++)
#pragma unroll
        for (int j = 0; j < 4; j++)
#pragma unroll
            for (int r = 0; r < 4; r++) acc[i][j][r] = 0.f;

    hmma_mainloop(sb, acc, Ah, Al, Bh, Bl, bm, bn, K, lda, ldb, tid, lane, wm, wn);

    int lr = lane >> 2, lc = (lane & 3) * 2;
#pragma unroll
    for (int mt = 0; mt < 4; mt++) {
#pragma unroll
        for (int nt = 0; nt < 4; nt++) {
            float* a = acc[mt][nt];
            int m0 = bm + wm * 64 + mt * 16 + lr;
            int n0 = bn + wn * 32 + nt * 8 + lc;
            float2* p0 = (float2*)(C + (size_t)m0 * N + n0);
            float2* p1 = (float2*)(C + (size_t)(m0 + 8) * N + n0);
            float2 v0 = *p0, v1 = *p1;
            v0.x += a[0]; v0.y += a[1];
            v1.x += a[2]; v1.y += a[3];
            *p0 = v0; *p1 = v1;
        }
    }
}

// ================= HMMA flash attention =================
// K/V double-buffered (2 x AT_BUF) + dedicated persistent Q region (hi/lo planes).
// Q fragments are re-loaded from smem per k-chunk -> low register pressure -> 2 CTAs/SM.
#define AT_STRIDE 144
#define AT_PLANE (64 * AT_STRIDE)      // 9216 B
#define AT_BUF   (4 * AT_PLANE)        // kh, kl, vth, vtl : 36864 B
#define AT_QOFF  (2 * AT_BUF)          // Q hi plane (128 x 144 B)
#define AT_QLO   (128 * AT_STRIDE)     // Q lo plane offset from AT_QOFF
#define AT_SMEM  (2 * AT_BUF + 2 * 128 * AT_STRIDE)   // 110592 B

__device__ __forceinline__ void at_load_tile(
    uint32_t dst, const __nv_bfloat16* kh, const __nv_bfloat16* kl,
    const __nv_bfloat16* vth, const __nv_bfloat16* vtl,
    int head, int kt, int tid)
{
    int row = tid >> 2, q4 = tid & 3;
    size_t koff = (size_t)(kt * 64 + row) * D + head * DH + q4 * 16;
    uint32_t d = dst + row * AT_STRIDE + q4 * 32;
    cp16(d,                    kh + koff);
    cp16(d + 16,               kh + koff + 8);
    cp16(d + AT_PLANE,         kl + koff);
    cp16(d + AT_PLANE + 16,    kl + koff + 8);
    size_t voff = (size_t)(head * DH + row) * S + kt * 64 + q4 * 16;
    cp16(d + 2 * AT_PLANE,      vth + voff);
    cp16(d + 2 * AT_PLANE + 16, vth + voff + 8);
    cp16(d + 3 * AT_PLANE,      vtl + voff);
    cp16(d + 3 * AT_PLANE + 16, vtl + voff + 8);
}

__global__ void __launch_bounds__(256, 2) hmma_attn(
    const __nv_bfloat16* __restrict__ qh, const __nv_bfloat16* __restrict__ ql,
    const __nv_bfloat16* __restrict__ kh, const __nv_bfloat16* __restrict__ kl,
    const __nv_bfloat16* __restrict__ vth, const __nv_bfloat16* __restrict__ vtl,
    uint32_t* __restrict__ acth, uint32_t* __restrict__ actl)
{
    extern __shared__ __align__(128) char smem[];
    uint32_t sb = smem_u32(smem);
    int tid = threadIdx.x, lane = tid & 31, wid = tid >> 5;
    int qt = (int)gridDim.x - 1 - (int)blockIdx.x;   // heavy tiles first
    int head = blockIdx.y;
    int ntiles = 2 * qt + 2;

    // Q tile (128x64, hi/lo) into its own persistent region
    {
        int row = tid >> 1, half = tid & 1;
        const __nv_bfloat16* s0 = qh + (size_t)(qt * 128 + row) * D + head * DH + half * 32;
        const __nv_bfloat16* s1 = ql + (size_t)(qt * 128 + row) * D + head * DH + half * 32;
        uint32_t dq = sb + AT_QOFF + row * AT_STRIDE + half * 64;
        cp16(dq,      s0); cp16(dq + 16, s0 + 8);
        cp16(dq + 32, s0 + 16); cp16(dq + 48, s0 + 24);
        uint32_t dl = dq + AT_QLO;
        cp16(dl,      s1); cp16(dl + 16, s1 + 8);
        cp16(dl + 32, s1 + 16); cp16(dl + 48, s1 + 24);
    }
    CP_COMMIT();                                        // group: Q
    at_load_tile(sb, kh, kl, vth, vtl, head, 0, tid);
    CP_COMMIT();                                        // group: tile 0
    if (ntiles > 1) { at_load_tile(sb + AT_BUF, kh, kl, vth, vtl, head, 1, tid); CP_COMMIT(); }

    float oacc[8][4];
#pragma unroll
    for (int i = 0; i < 8; i++)
#pragma unroll
        for (int j = 0; j < 4; j++) oacc[i][j] = 0.f;
    float m0 = -INFINITY, m1 = -INFINITY, l0 = 0.f, l1 = 0.f;
    int row0 = qt * 128 + wid * 16 + (lane >> 2);
    uint32_t q_base = sb + AT_QOFF + (wid * 16 + (lane & 15)) * AT_STRIDE + ((lane >> 4) & 1) * 16;

    for (int kt = 0; kt < ntiles; kt++) {
        if (kt + 1 < ntiles) CP_WAIT1(); else CP_WAIT0();   // Q done by first wait too
        __syncthreads();
        uint32_t base = sb + (kt & 1) * AT_BUF;

        if (kt * 64 <= qt * 128 + wid * 16 + 15) {
            float s[8][4];
#pragma unroll
            for (int i = 0; i < 8; i++)
#pragma unroll
                for (int j = 0; j < 4; j++) s[i][j] = 0.f;

            // S = Q @ K^T (3-term), Q fragments re-loaded per k-chunk from smem
#pragma unroll
            for (int kc = 0; kc < 4; kc++) {
                uint32_t qh_f[4], ql_f[4];
                ldmx4(qh_f, q_base + kc * 32);
                ldmx4(ql_f, q_base + AT_QLO + kc * 32);
                uint32_t koff = ((lane & 8) << 1) + kc * 32;
#pragma unroll
                for (int nt = 0; nt < 8; nt++) {
                    uint32_t ka = base + (nt * 8 + (lane & 7)) * AT_STRIDE + koff;
                    uint32_t bh[2], bl[2];
                    ldmx2(bh, ka);
                    ldmx2(bl, ka + AT_PLANE);
                    mma16816(s[nt], qh_f, bh);
                    mma16816(s[nt], qh_f, bl);
                    mma16816(s[nt], ql_f, bh);
                }
            }

            if (kt >= 2 * qt) {
#pragma unroll
                for (int nt = 0; nt < 8; nt++) {
                    int c = kt * 64 + nt * 8 + 2 * (lane & 3);
                    if (c     > row0)     s[nt][0] = -INFINITY;
                    if (c + 1 > row0)     s[nt][1] = -INFINITY;
                    if (c     > row0 + 8) s[nt][2] = -INFINITY;
                    if (c + 1 > row0 + 8) s[nt][3] = -INFINITY;
                }
            }

            float mx0 = -INFINITY, mx1 = -INFINITY;
#pragma unroll
            for (int nt = 0; nt < 8; nt++) {
                mx0 = fmaxf(mx0, fmaxf(s[nt][0], s[nt][1]));
                mx1 = fmaxf(mx1, fmaxf(s[nt][2], s[nt][3]));
            }
            mx0 = fmaxf(mx0, __shfl_xor_sync(0xffffffffu, mx0, 1));
            mx0 = fmaxf(mx0, __shfl_xor_sync(0xffffffffu, mx0, 2));
            mx1 = fmaxf(mx1, __shfl_xor_sync(0xffffffffu, mx1, 1));
            mx1 = fmaxf(mx1, __shfl_xor_sync(0xffffffffu, mx1, 2));
            float nm0 = fmaxf(m0, mx0), nm1 = fmaxf(m1, mx1);
            float a0 = __expf(m0 - nm0), a1 = __expf(m1 - nm1);
            m0 = nm0; m1 = nm1;
            float ps0 = 0.f, ps1 = 0.f;
#pragma unroll
            for (int nt = 0; nt < 8; nt++) {
                s[nt][0] = __expf(s[nt][0] - m0); ps0 += s[nt][0];
                s[nt][1] = __expf(s[nt][1] - m0); ps0 += s[nt][1];
                s[nt][2] = __expf(s[nt][2] - m1); ps1 += s[nt][2];
                s[nt][3] = __expf(s[nt][3] - m1); ps1 += s[nt][3];
            }
            l0 = l0 * a0 + ps0;
            l1 = l1 * a1 + ps1;
#pragma unroll
            for (int dt = 0; dt < 8; dt++) {
                oacc[dt][0] *= a0; oacc[dt][1] *= a0;
                oacc[dt][2] *= a1; oacc[dt][3] *= a1;
            }

#pragma unroll
            for (int kc = 0; kc < 4; kc++) {
                uint32_t ph[4], pl[4];
                packsplit(ph[0], pl[0], s[2 * kc][0],     s[2 * kc][1]);
                packsplit(ph[1], pl[1], s[2 * kc][2],     s[2 * kc][3]);
                packsplit(ph[2], pl[2], s[2 * kc + 1][0], s[2 * kc + 1][1]);
                packsplit(ph[3], pl[3], s[2 * kc + 1][2], s[2 * kc + 1][3]);
                uint32_t koff = ((lane & 8) << 1) + kc * 32;
#pragma unroll
                for (int dt = 0; dt < 8; dt++) {
                    uint32_t va = base + 2 * AT_PLANE + (dt * 8 + (lane & 7)) * AT_STRIDE + koff;
                    uint32_t vh[2], vl[2];
                    ldmx2(vh, va);
                    ldmx2(vl, va + AT_PLANE);
                    mma16816(oacc[dt], ph, vh);
                    mma16816(oacc[dt], ph, vl);
                    mma16816(oacc[dt], pl, vh);
                }
            }
        }
        __syncthreads();
        if (kt + 2 < ntiles) { at_load_tile(base, kh, kl, vth, vtl, head, kt + 2, tid); CP_COMMIT(); }
    }

    l0 += __shfl_xor_sync(0xffffffffu, l0, 1);
    l0 += __shfl_xor_sync(0xffffffffu, l0, 2);
    l1 += __shfl_xor_sync(0xffffffffu, l1, 1);
    l1 += __shfl_xor_sync(0xffffffffu, l1, 2);
    float i0 = 1.f / l0, i1 = 1.f / l1;
#pragma unroll
    for (int dt = 0; dt < 8; dt++) {
        int col = F + head * DH + dt * 8 + 2 * (lane & 3);
        uint32_t h0, lo0, h1, lo1;
        packsplit(h0, lo0, oacc[dt][0] * i0, oacc[dt][1] * i0);
        packsplit(h1, lo1, oacc[dt][2] * i1, oacc[dt][3] * i1);
        size_t i0x = (size_t)row0 * (K2 / 2) + (col >> 1);
        size_t i1x = (size_t)(row0 + 8) * (K2 / 2) + (col >> 1);
        acth[i0x] = h0; actl[i0x] = lo0;
        acth[i1x] = h1; actl[i1x] = lo1;
    }
}

// ---------------- out = x + b_mo + b_ao ----------------
__global__ void init_out_kernel(const float* __restrict__ x,
                                const float* __restrict__ bmo,
                                const float* __restrict__ bao,
                                float* __restrict__ out) {
    int i = blockIdx.x * blockDim.x + threadIdx.x;
    int col = i & (D - 1);
    out[i] = x[i] + bmo[col] + bao[col];
}

// ---------------- launch (fork-join graph: side stream overlaps h@w_mo with attention) ----------------
extern "C" void kernel_launch(void* const* d_in, const int* in_sizes, int n_in,
                              void* d_out, int out_size) {
    const float* x        = (const float*)d_in[0];
    // d_in[1] = mask (causal tril) handled analytically
    const float* ln_scale = (const float*)d_in[2];
    const float* ln_bias  = (const float*)d_in[3];
    const float* w_in     = (const float*)d_in[4];
    const float* b_in     = (const float*)d_in[5];
    const float* wq       = (const float*)d_in[6];
    const float* bq       = (const float*)d_in[7];
    const float* wk       = (const float*)d_in[8];
    const float* bk       = (const float*)d_in[9];
    const float* wv       = (const float*)d_in[10];
    const float* bv       = (const float*)d_in[11];
    const float* qn       = (const float*)d_in[12];
    const float* kn       = (const float*)d_in[13];
    const float* w_mo     = (const float*)d_in[14];
    const float* b_mo     = (const float*)d_in[15];
    const float* w_ao     = (const float*)d_in[16];
    const float* b_ao     = (const float*)d_in[17];
    float* out = (float*)d_out;

    float *q, *k, *v;
    cudaGetSymbolAddress((void**)&q, g_q);
    cudaGetSymbolAddress((void**)&k, g_k);
    cudaGetSymbolAddress((void**)&v, g_v);

    __nv_bfloat16 *xnh, *xnl, *acth, *actl, *qsh, *qsl, *ksh, *ksl, *vth, *vtl;
    __nv_bfloat16 *w1h, *w1l, *w2h, *w2l;
    cudaGetSymbolAddress((void**)&xnh, g_xnh);   cudaGetSymbolAddress((void**)&xnl, g_xnl);
    cudaGetSymbolAddress((void**)&acth, g_acth); cudaGetSymbolAddress((void**)&actl, g_actl);
    cudaGetSymbolAddress((void**)&qsh, g_qsh);   cudaGetSymbolAddress((void**)&qsl, g_qsl);
    cudaGetSymbolAddress((void**)&ksh, g_ksh);   cudaGetSymbolAddress((void**)&ksl, g_ksl);
    cudaGetSymbolAddress((void**)&vth, g_vth);   cudaGetSymbolAddress((void**)&vtl, g_vtl);
    cudaGetSymbolAddress((void**)&w1h, g_w1h);   cudaGetSymbolAddress((void**)&w1l, g_w1l);
    cudaGetSymbolAddress((void**)&w2h, g_w2h);   cudaGetSymbolAddress((void**)&w2l, g_w2l);

    cudaFuncSetAttribute(hmma_gemm_f1,  cudaFuncAttributeMaxDynamicSharedMemorySize, GSMEM);
    cudaFuncSetAttribute(hmma_gemm_acc, cudaFuncAttributeMaxDynamicSharedMemorySize, GSMEM);
    cudaFuncSetAttribute(hmma_attn,     cudaFuncAttributeMaxDynamicSharedMemorySize, AT_SMEM);

    // lazily-created side stream + events (host resources only; per-call work identical)
    static cudaStream_t side = nullptr;
    static cudaEvent_t ev_fork = nullptr, ev_f1 = nullptr, ev_side = nullptr;
    if (!side) {
        cudaStreamCreateWithFlags(&side, cudaStreamNonBlocking);
        cudaEventCreateWithFlags(&ev_fork, cudaEventDisableTiming);
        cudaEventCreateWithFlags(&ev_f1,   cudaEventDisableTiming);
        cudaEventCreateWithFlags(&ev_side, cudaEventDisableTiming);
    }

    // fork side branch
    cudaEventRecord(ev_fork, 0);
    cudaStreamWaitEvent(side, ev_fork, 0);

    // side: w2 packing + out init (independent of main until h@w_mo)
    splitT_kernel<<<dim3(D / 32, F / 32), dim3(32, 8), 0, side>>>(w_mo, w2h, w2l, F, D, K2);
    splitT_kernel<<<dim3(D / 32, D / 32), dim3(32, 8), 0, side>>>(w_ao, w2h + F, w2l + F, D, D, K2);
    init_out_kernel<<<(S * D) / 256, 256, 0, side>>>(x, b_mo, b_ao, out);

    // main: w1 packing, LN, fused f1 GEMM
    splitT_kernel<<<dim3(F / 32, D / 32), dim3(32, 8)>>>(w_in, w1h, w1l, D, F, D);
    splitT_kernel<<<dim3(D / 32, D / 32), dim3(32, 8)>>>(wq, w1h + (size_t)F * D, w1l + (size_t)F * D, D, D, D);
    splitT_kernel<<<dim3(D / 32, D / 32), dim3(32, 8)>>>(wk, w1h + (size_t)(F + D) * D, w1l + (size_t)(F + D) * D, D, D, D);
    splitT_kernel<<<dim3(D / 32, D / 32), dim3(32, 8)>>>(wv, w1h + (size_t)(F + 2 * D) * D, w1l + (size_t)(F + 2 * D) * D, D, D, D);
    ln_split_kernel<<<S, 256>>>(x, ln_scale, ln_bias, (uint32_t*)xnh, (uint32_t*)xnl);
    hmma_gemm_f1<<<dim3(N1 / 128, S / 128), 256, GSMEM>>>(
        xnh, xnl, w1h, w1l, b_in, bq, bk, bv,
        (uint32_t*)acth, (uint32_t*)actl, q, k, v);
    cudaEventRecord(ev_f1, 0);

    // side: out += h @ w_mo (needs f1's h planes + its own w2/out) — overlaps attention path
    cudaStreamWaitEvent(side, ev_f1, 0);
    hmma_gemm_acc<<<dim3(D / 128, S / 128), 256, GSMEM, side>>>(
        acth, actl, w2h, w2l, out, D, F, K2, K2);
    cudaEventRecord(ev_side, side);

    // main: qk-norm + split, V split-transpose, attention
    qknorm_split<<<(S * H) / 256, 256>>>(q, qn, (uint32_t*)qsh, (uint32_t*)qsl, 0.125f);
    qknorm_split<<<(S * H) / 256, 256>>>(k, kn, (uint32_t*)ksh, (uint32_t*)ksl, 1.f);
    splitT_kernel<<<dim3(D / 32, S / 32), dim3(32, 8)>>>(v, vth, vtl, S, D, S);
    hmma_attn<<<dim3(S / 128, H), 256, AT_SMEM>>>(qsh, qsl, ksh, ksl, vth, vtl,
                                                  (uint32_t*)acth, (uint32_t*)actl);

    // join, then out += o @ w_ao (K window [4096, 5120))
    cudaStreamWaitEvent(0, ev_side, 0);
    hmma_gemm_acc<<<dim3(D / 128, S / 128), 256, GSMEM>>>(
        acth + F, actl + F, w2h + F, w2l + F, out, D, D, K2, K2);
}